// round 7
// baseline (speedup 1.0000x reference)
#include <cuda_runtime.h>
#include <cuda_fp16.h>
#include <math.h>

// Problem constants (fixed by the dataset)
#define Bc   4
#define Nc   50000
#define EcMax 800000
#define INc  128
#define Hc   4
#define Dc   32
#define HDc  128
#define BNc  (Bc * Nc)          // 200000 rows
#define GAT_SLOPE 0.2f
#define ACT_SLOPE 0.01f
#define BN_EPS    1e-5f

// ---------------- scratch (device globals; no allocation allowed) ----------
// Invariant discipline: every global that must be zero at kernel-launch entry
// is zeroed by the kernel that CONSUMES it, so graph replays are deterministic.
__device__ __half   g_featH[(size_t)BNc * HDc]; // 51.2 MB (fp16 features)
__device__ float4   g_el[BNc];                  // per-node, per-head (4 heads)
__device__ float4   g_er[BNc];
__device__ int      g_cnt[Nc];                  // in-degree histogram (zeroed by k_scan)
__device__ int      g_off[Nc + 1];              // CSR offsets
__device__ int      g_wr[Nc];                   // scatter write cursors
__device__ int      g_csrc[EcMax];              // CSR: src node per slot
__device__ float    g_sum[HDc];                 // zeroed by k_bnfinal
__device__ float    g_sq[HDc];                  // zeroed by k_bnfinal
__device__ float    g_scale[HDc];
__device__ float    g_shift[HDc];

__device__ __forceinline__ float leaky(float v, float s) {
    return v >= 0.0f ? v : s * v;
}

__device__ __forceinline__ unsigned f2tf32(float f) {
    unsigned u;
    asm("cvt.rna.tf32.f32 %0, %1;" : "=r"(u) : "f"(f));
    return u;
}

__device__ __forceinline__ void mma_tf32(float* c, const unsigned* a,
                                         unsigned b0, unsigned b1) {
    asm volatile(
        "mma.sync.aligned.m16n8k8.row.col.f32.tf32.tf32.f32 "
        "{%0,%1,%2,%3}, {%4,%5,%6,%7}, {%8,%9}, {%0,%1,%2,%3};"
        : "+f"(c[0]), "+f"(c[1]), "+f"(c[2]), "+f"(c[3])
        : "r"(a[0]), "r"(a[1]), "r"(a[2]), "r"(a[3]), "r"(b0), "r"(b1));
}

// ---------------- CSR build --------------------------------------------------
__global__ void k_hist(const int* __restrict__ dst, int E) {
    int e = blockIdx.x * blockDim.x + threadIdx.x;
    if (e < E) atomicAdd(&g_cnt[dst[e]], 1);
}

// single block, 1024 threads: exclusive scan of g_cnt -> g_off/g_wr,
// then restore g_cnt to zero (consumes the histogram).
__global__ void k_scan() {
    __shared__ int ssum[1024];
    const int t = threadIdx.x;
    const int per = (Nc + 1023) / 1024;   // 49
    const int base = t * per;
    int s = 0;
    for (int i = 0; i < per; i++) {
        int idx = base + i;
        if (idx < Nc) s += g_cnt[idx];
    }
    ssum[t] = s;
    __syncthreads();
    for (int o = 1; o < 1024; o <<= 1) {
        int v = (t >= o) ? ssum[t - o] : 0;
        __syncthreads();
        ssum[t] += v;
        __syncthreads();
    }
    int run = ssum[t] - s;
    for (int i = 0; i < per; i++) {
        int idx = base + i;
        if (idx < Nc) {
            g_off[idx] = run;
            g_wr[idx]  = run;
            run += g_cnt[idx];
            g_cnt[idx] = 0;      // restore invariant for next replay
        }
    }
    if (t == 1023) g_off[Nc] = ssum[1023];
}

__global__ void k_scatter(const int* __restrict__ src, const int* __restrict__ dst, int E) {
    int e = blockIdx.x * blockDim.x + threadIdx.x;
    if (e < E) {
        int pos = atomicAdd(&g_wr[dst[e]], 1);
        g_csrc[pos] = src[e];
    }
}

// ---------------- 1: feat = x @ W via tf32 mma, single-stage full-K tiles ---
// Block: 256 threads (8 warps, 2m x 4n). Block tile 128 rows x 128 cols.
#define XS_LD 132
#define WS_LD 136
#define SMEM_GEMM ((128 * XS_LD + 128 * WS_LD + 1024) * 4)
__global__ void __launch_bounds__(256, 1)
k_gemm(const float* __restrict__ x, const float* __restrict__ W,
       const float* __restrict__ attn_l, const float* __restrict__ attn_r) {
    extern __shared__ float smem[];
    float* xs  = smem;                       // [128][XS_LD]
    float* Ws  = smem + 128 * XS_LD;         // [128][WS_LD]
    float* sEl = Ws + 128 * WS_LD;           // [128][4]
    float* sEr = sEl + 512;                  // [128][4]

    const int t = threadIdx.x;
    const int lane = t & 31, warp = t >> 5;
    const int wm = warp >> 2, wn = warp & 3;   // warp grid 2 x 4
    const int gid = lane >> 2, tig = lane & 3;
    const int row0 = blockIdx.x * 128;

    sEl[t] = 0.f; sEl[t + 256] = 0.f;
    sEr[t] = 0.f; sEr[t + 256] = 0.f;

#pragma unroll
    for (int i = 0; i < 16; i++) {
        int idx = i * 256 + t;
        int k = idx >> 5, c4 = idx & 31;
        float4 v = *(const float4*)(W + (size_t)k * 128 + c4 * 4);
        float* dstp = &Ws[k * WS_LD + c4 * 4];
        dstp[0] = __uint_as_float(f2tf32(v.x));
        dstp[1] = __uint_as_float(f2tf32(v.y));
        dstp[2] = __uint_as_float(f2tf32(v.z));
        dstp[3] = __uint_as_float(f2tf32(v.w));
    }
#pragma unroll
    for (int i = 0; i < 16; i++) {
        int idx = i * 256 + t;
        int r = idx >> 5, c4 = idx & 31;
        int grow = row0 + r;
        float4 v = make_float4(0.f, 0.f, 0.f, 0.f);
        if (grow < BNc)
            v = *(const float4*)(x + (size_t)grow * 128 + c4 * 4);
        float* dstp = &xs[r * XS_LD + c4 * 4];
        dstp[0] = __uint_as_float(f2tf32(v.x));
        dstp[1] = __uint_as_float(f2tf32(v.y));
        dstp[2] = __uint_as_float(f2tf32(v.z));
        dstp[3] = __uint_as_float(f2tf32(v.w));
    }
    __syncthreads();

    float acc[4][4][4];
#pragma unroll
    for (int i = 0; i < 4; i++)
#pragma unroll
        for (int j = 0; j < 4; j++)
#pragma unroll
            for (int r = 0; r < 4; r++) acc[i][j][r] = 0.f;

#pragma unroll
    for (int ks = 0; ks < 16; ks++) {
        const int k0 = ks * 8;
        unsigned a[4][4];
#pragma unroll
        for (int mt = 0; mt < 4; mt++) {
            int rb = wm * 64 + mt * 16;
            a[mt][0] = __float_as_uint(xs[(rb + gid) * XS_LD + k0 + tig]);
            a[mt][1] = __float_as_uint(xs[(rb + gid + 8) * XS_LD + k0 + tig]);
            a[mt][2] = __float_as_uint(xs[(rb + gid) * XS_LD + k0 + tig + 4]);
            a[mt][3] = __float_as_uint(xs[(rb + gid + 8) * XS_LD + k0 + tig + 4]);
        }
#pragma unroll
        for (int nt = 0; nt < 4; nt++) {
            int cb = wn * 32 + nt * 8;
            unsigned b0 = __float_as_uint(Ws[(k0 + tig) * WS_LD + cb + gid]);
            unsigned b1 = __float_as_uint(Ws[(k0 + tig + 4) * WS_LD + cb + gid]);
#pragma unroll
            for (int mt = 0; mt < 4; mt++)
                mma_tf32(acc[mt][nt], a[mt], b0, b1);
        }
    }

    // epilogue: store feat (fp16) + accumulate el/er into smem
#pragma unroll
    for (int mt = 0; mt < 4; mt++) {
        int lr0 = wm * 64 + mt * 16 + gid;
        int lr1 = lr0 + 8;
        float el0 = 0.f, el1 = 0.f, er0 = 0.f, er1 = 0.f;
#pragma unroll
        for (int nt = 0; nt < 4; nt++) {
            int c = wn * 32 + nt * 8 + tig * 2;
            float alc0 = attn_l[c], alc1 = attn_l[c + 1];
            float arc0 = attn_r[c], arc1 = attn_r[c + 1];
            float* a4 = acc[mt][nt];
            el0 += a4[0] * alc0 + a4[1] * alc1;
            er0 += a4[0] * arc0 + a4[1] * arc1;
            el1 += a4[2] * alc0 + a4[3] * alc1;
            er1 += a4[2] * arc0 + a4[3] * arc1;
            if (row0 + lr0 < BNc)
                *(__half2*)(g_featH + (size_t)(row0 + lr0) * 128 + c) =
                    __floats2half2_rn(a4[0], a4[1]);
            if (row0 + lr1 < BNc)
                *(__half2*)(g_featH + (size_t)(row0 + lr1) * 128 + c) =
                    __floats2half2_rn(a4[2], a4[3]);
        }
        atomicAdd(&sEl[lr0 * 4 + wn], el0);
        atomicAdd(&sEl[lr1 * 4 + wn], el1);
        atomicAdd(&sEr[lr0 * 4 + wn], er0);
        atomicAdd(&sEr[lr1 * 4 + wn], er1);
    }
    __syncthreads();
    if (t < 128 && row0 + t < BNc) {
        g_el[row0 + t] = make_float4(sEl[t * 4], sEl[t * 4 + 1], sEl[t * 4 + 2], sEl[t * 4 + 3]);
        g_er[row0 + t] = make_float4(sEr[t * 4], sEr[t * 4 + 1], sEr[t * 4 + 2], sEr[t * 4 + 3]);
    }
}

// ---------------- 2: fused edge-softmax + gather aggregation ----------------
// grid (Nc, Bc), 64 threads: thread = one half2 channel pair; block = node.
// (Round-4 structure: chunked smem weights; many small blocks give the
//  scheduler enough parallel gather chains to hide L2 latency.)
// Softmax without max-subtraction: exp(e)/sum(exp(e)) identical; |e| small.
#define CH 64
__global__ void k_agg(float* __restrict__ out) {
    const int n = blockIdx.x, b = blockIdx.y;
    const int tid = threadIdx.x;          // 0..63, channels 2t, 2t+1
    const int h = tid >> 4;               // head = (2t)/32
    const int off0 = g_off[n];
    const int deg  = g_off[n + 1] - off0;
    const size_t nb = (size_t)b * Nc + n;

    if (deg == 0) {
        *(float2*)(out + nb * 128 + tid * 2) = make_float2(0.f, 0.f);
        return;
    }

    __shared__ float sw[CH][4];
    __shared__ int   ssrc[CH];

    const float4 er4 = g_er[nb];

    float ax = 0.f, ay = 0.f, wsum = 0.f;
    for (int base = 0; base < deg; base += CH) {
        int cnt = min(CH, deg - base);
        if (tid < cnt) {
            int s = g_csrc[off0 + base + tid];
            ssrc[tid] = s;
            float4 el4 = g_el[(size_t)b * Nc + s];
            sw[tid][0] = __expf(leaky(el4.x + er4.x, GAT_SLOPE));
            sw[tid][1] = __expf(leaky(el4.y + er4.y, GAT_SLOPE));
            sw[tid][2] = __expf(leaky(el4.z + er4.z, GAT_SLOPE));
            sw[tid][3] = __expf(leaky(el4.w + er4.w, GAT_SLOPE));
        }
        __syncthreads();
#pragma unroll 4
        for (int j = 0; j < cnt; j++) {
            float ww = sw[j][h];
            wsum += ww;
            __half2 f = *(const __half2*)(g_featH +
                         ((size_t)b * Nc + ssrc[j]) * 128 + tid * 2);
            float2 ff = __half22float2(f);
            ax += ww * ff.x;
            ay += ww * ff.y;
        }
        __syncthreads();
    }
    float inv = 1.f / fmaxf(wsum, 1e-9f);
    *(float2*)(out + nb * 128 + tid * 2) = make_float2(ax * inv, ay * inv);
}

// ---------------- 3: BN statistics (float4 loads) ----------------------------
__global__ void k_bnstats(const float4* __restrict__ out4) {
    int c4 = threadIdx.x & 31;                 // float4 slot within row
    int r = blockIdx.x * 8 + (threadIdx.x >> 5);
    float4 s = make_float4(0.f, 0.f, 0.f, 0.f);
    float4 q = make_float4(0.f, 0.f, 0.f, 0.f);
    for (; r < BNc; r += gridDim.x * 8) {
        float4 v = out4[(size_t)r * 32 + c4];
        s.x += v.x; s.y += v.y; s.z += v.z; s.w += v.w;
        q.x += v.x * v.x; q.y += v.y * v.y; q.z += v.z * v.z; q.w += v.w * v.w;
    }
    int c = c4 * 4;
    atomicAdd(&g_sum[c + 0], s.x); atomicAdd(&g_sum[c + 1], s.y);
    atomicAdd(&g_sum[c + 2], s.z); atomicAdd(&g_sum[c + 3], s.w);
    atomicAdd(&g_sq[c + 0], q.x);  atomicAdd(&g_sq[c + 1], q.y);
    atomicAdd(&g_sq[c + 2], q.z);  atomicAdd(&g_sq[c + 3], q.w);
}

__global__ void k_bnfinal(const float* __restrict__ gamma, const float* __restrict__ beta) {
    int c = threadIdx.x;
    float mean = g_sum[c] / (float)BNc;
    float var  = g_sq[c] / (float)BNc - mean * mean;
    float sc = gamma[c] * rsqrtf(var + BN_EPS);
    g_scale[c] = sc;
    g_shift[c] = beta[c] - mean * sc;
    g_sum[c] = 0.f;   // restore invariant for next replay
    g_sq[c]  = 0.f;
}

// ---------------- 4: BN apply + LeakyReLU (in place) -------------------------
__global__ void k_bnapply(float4* out) {
    int i = blockIdx.x * blockDim.x + threadIdx.x;
    int stride = gridDim.x * blockDim.x;
    const int n4 = BNc * HDc / 4;
    for (int p = i; p < n4; p += stride) {
        float4 v = out[p];
        int c = (p & 31) * 4;
        v.x = leaky(v.x * g_scale[c + 0] + g_shift[c + 0], ACT_SLOPE);
        v.y = leaky(v.y * g_scale[c + 1] + g_shift[c + 1], ACT_SLOPE);
        v.z = leaky(v.z * g_scale[c + 2] + g_shift[c + 2], ACT_SLOPE);
        v.w = leaky(v.w * g_scale[c + 3] + g_shift[c + 3], ACT_SLOPE);
        out[p] = v;
    }
}

// ---------------- launch -----------------------------------------------------
extern "C" void kernel_launch(void* const* d_in, const int* in_sizes, int n_in,
                              void* d_out, int out_size) {
    const float* xx     = (const float*)d_in[0];
    const float* W      = (const float*)d_in[1];
    const float* attn_l = (const float*)d_in[2];
    const float* attn_r = (const float*)d_in[3];
    const float* gamma  = (const float*)d_in[4];
    const float* beta   = (const float*)d_in[5];
    const int*   src    = (const int*)d_in[6];
    const int*   dst    = (const int*)d_in[7];
    float* out = (float*)d_out;
    const int E = in_sizes[6];

    static cudaStream_t s2 = nullptr;
    static cudaEvent_t evFork = nullptr, evJoin = nullptr;
    if (s2 == nullptr) {
        cudaStreamCreateWithFlags(&s2, cudaStreamNonBlocking);
        cudaEventCreateWithFlags(&evFork, cudaEventDisableTiming);
        cudaEventCreateWithFlags(&evJoin, cudaEventDisableTiming);
        cudaFuncSetAttribute(k_gemm, cudaFuncAttributeMaxDynamicSharedMemorySize,
                             SMEM_GEMM);
    }

    // fork: CSR build on s2, GEMM on main stream (independent work)
    cudaEventRecord(evFork, 0);
    cudaStreamWaitEvent(s2, evFork, 0);

    k_hist<<<(E + 511) / 512, 512, 0, s2>>>(dst, E);
    k_scan<<<1, 1024, 0, s2>>>();
    k_scatter<<<(E + 511) / 512, 512, 0, s2>>>(src, dst, E);
    cudaEventRecord(evJoin, s2);

    k_gemm<<<(BNc + 127) / 128, 256, SMEM_GEMM>>>(xx, W, attn_l, attn_r);

    cudaStreamWaitEvent(0, evJoin, 0);

    dim3 gagg(Nc, Bc);
    k_agg<<<gagg, 64>>>(out);

    k_bnstats<<<740, 256>>>((const float4*)out);
    k_bnfinal<<<1, 128>>>(gamma, beta);
    k_bnapply<<<2048, 256>>>((float4*)out);
}

// round 8
// speedup vs baseline: 1.2386x; 1.2386x over previous
#include <cuda_runtime.h>
#include <cuda_fp16.h>
#include <math.h>

// Problem constants (fixed by the dataset)
#define Bc   4
#define Nc   50000
#define EcMax 800000
#define INc  128
#define Hc   4
#define Dc   32
#define HDc  128
#define BNc  (Bc * Nc)          // 200000 rows
#define GAT_SLOPE 0.2f
#define ACT_SLOPE 0.01f
#define BN_EPS    1e-5f

// ---------------- scratch (device globals; no allocation allowed) ----------
__device__ __half   g_featH[(size_t)BNc * HDc]; // 51.2 MB (fp16 features)
__device__ float4   g_el[BNc];                  // per-node, per-head (4 heads)
__device__ float4   g_er[BNc];
__device__ int      g_cnt[Nc];                  // in-degree histogram
__device__ int      g_off[Nc + 1];              // CSR offsets
__device__ int      g_wr[Nc];                   // scatter write cursors
__device__ int      g_csrc[EcMax];              // CSR: src node per slot
__device__ float    g_sum[HDc];
__device__ float    g_sq[HDc];
__device__ float    g_scale[HDc];
__device__ float    g_shift[HDc];

__device__ __forceinline__ float leaky(float v, float s) {
    return v >= 0.0f ? v : s * v;
}

__device__ __forceinline__ unsigned f2tf32(float f) {
    unsigned u;
    asm("cvt.rna.tf32.f32 %0, %1;" : "=r"(u) : "f"(f));
    return u;
}

__device__ __forceinline__ void mma_tf32(float* c, const unsigned* a,
                                         unsigned b0, unsigned b1) {
    asm volatile(
        "mma.sync.aligned.m16n8k8.row.col.f32.tf32.tf32.f32 "
        "{%0,%1,%2,%3}, {%4,%5,%6,%7}, {%8,%9}, {%0,%1,%2,%3};"
        : "+f"(c[0]), "+f"(c[1]), "+f"(c[2]), "+f"(c[3])
        : "r"(a[0]), "r"(a[1]), "r"(a[2]), "r"(a[3]), "r"(b0), "r"(b1));
}

// ---------------- 0: zero-init histogram + BN accumulators ------------------
__global__ void k_init() {
    int i = blockIdx.x * blockDim.x + threadIdx.x;
    int stride = gridDim.x * blockDim.x;
    for (int p = i; p < Nc; p += stride) g_cnt[p] = 0;
    if (i < HDc) { g_sum[i] = 0.f; g_sq[i] = 0.f; }
}

// ---------------- CSR build --------------------------------------------------
__global__ void k_hist(const int* __restrict__ dst, int E) {
    int e = blockIdx.x * blockDim.x + threadIdx.x;
    if (e < E) atomicAdd(&g_cnt[dst[e]], 1);
}

__global__ void k_scan() {
    __shared__ int ssum[1024];
    const int t = threadIdx.x;
    const int per = (Nc + 1023) / 1024;   // 49
    const int base = t * per;
    int s = 0;
    for (int i = 0; i < per; i++) {
        int idx = base + i;
        if (idx < Nc) s += g_cnt[idx];
    }
    ssum[t] = s;
    __syncthreads();
    for (int o = 1; o < 1024; o <<= 1) {
        int v = (t >= o) ? ssum[t - o] : 0;
        __syncthreads();
        ssum[t] += v;
        __syncthreads();
    }
    int run = ssum[t] - s;
    for (int i = 0; i < per; i++) {
        int idx = base + i;
        if (idx < Nc) {
            g_off[idx] = run;
            g_wr[idx]  = run;
            run += g_cnt[idx];
        }
    }
    if (t == 1023) g_off[Nc] = ssum[1023];
}

__global__ void k_scatter(const int* __restrict__ src, const int* __restrict__ dst, int E) {
    int e = blockIdx.x * blockDim.x + threadIdx.x;
    if (e < E) {
        int pos = atomicAdd(&g_wr[dst[e]], 1);
        g_csrc[pos] = src[e];
    }
}

// ---------------- 1: feat = x @ W via tf32 mma, fused el/er epilogue --------
// Occupancy-oriented tiling: block 256 threads (8 warps, 2m x 4n),
// block tile 64 rows x 128 cols, warp tile 32x32, k staged in 32-chunks.
// ~29 KB smem, ~32 acc regs/thread -> ~3 CTAs/SM (vs 1 before).
// 200000 rows = 3125 * 64 exactly: no row guards needed.
__global__ void __launch_bounds__(256)
k_gemm(const float* __restrict__ x, const float* __restrict__ W,
       const float* __restrict__ attn_l, const float* __restrict__ attn_r) {
    __shared__ float xs[64][36];     // [row][k], pad 36
    __shared__ float Ws[32][136];    // [k][col], pad 136
    __shared__ float sEl[64][4];
    __shared__ float sEr[64][4];

    const int t = threadIdx.x;
    const int lane = t & 31, warp = t >> 5;
    const int wm = warp >> 2, wn = warp & 3;   // warp grid 2m x 4n
    const int gid = lane >> 2, tig = lane & 3;
    const int row0 = blockIdx.x * 64;

    ((float*)sEl)[t] = 0.f;
    ((float*)sEr)[t] = 0.f;

    float acc[2][4][4];
#pragma unroll
    for (int i = 0; i < 2; i++)
#pragma unroll
        for (int j = 0; j < 4; j++)
#pragma unroll
            for (int r = 0; r < 4; r++) acc[i][j][r] = 0.f;

    for (int kc = 0; kc < 128; kc += 32) {
        // stage W chunk [32 k][128 c]: 1024 float4, 4 per thread
#pragma unroll
        for (int i = 0; i < 4; i++) {
            int idx = i * 256 + t;
            int k = idx >> 5, c4 = idx & 31;
            float4 v = *(const float4*)(W + (size_t)(kc + k) * 128 + c4 * 4);
            float* dstp = &Ws[k][c4 * 4];
            dstp[0] = __uint_as_float(f2tf32(v.x));
            dstp[1] = __uint_as_float(f2tf32(v.y));
            dstp[2] = __uint_as_float(f2tf32(v.z));
            dstp[3] = __uint_as_float(f2tf32(v.w));
        }
        // stage x chunk [64 r][32 k]: 512 float4, 2 per thread
#pragma unroll
        for (int i = 0; i < 2; i++) {
            int idx = i * 256 + t;
            int r = idx >> 3, c4 = idx & 7;
            float4 v = *(const float4*)(x + (size_t)(row0 + r) * 128 + kc + c4 * 4);
            float* dstp = &xs[r][c4 * 4];
            dstp[0] = __uint_as_float(f2tf32(v.x));
            dstp[1] = __uint_as_float(f2tf32(v.y));
            dstp[2] = __uint_as_float(f2tf32(v.z));
            dstp[3] = __uint_as_float(f2tf32(v.w));
        }
        __syncthreads();

#pragma unroll
        for (int ks = 0; ks < 4; ks++) {
            const int k0 = ks * 8;
            unsigned a[2][4];
#pragma unroll
            for (int mt = 0; mt < 2; mt++) {
                int rb = wm * 32 + mt * 16;
                a[mt][0] = __float_as_uint(xs[rb + gid][k0 + tig]);
                a[mt][1] = __float_as_uint(xs[rb + gid + 8][k0 + tig]);
                a[mt][2] = __float_as_uint(xs[rb + gid][k0 + tig + 4]);
                a[mt][3] = __float_as_uint(xs[rb + gid + 8][k0 + tig + 4]);
            }
#pragma unroll
            for (int nt = 0; nt < 4; nt++) {
                int cb = wn * 32 + nt * 8;
                unsigned b0 = __float_as_uint(Ws[k0 + tig][cb + gid]);
                unsigned b1 = __float_as_uint(Ws[k0 + tig + 4][cb + gid]);
#pragma unroll
                for (int mt = 0; mt < 2; mt++)
                    mma_tf32(acc[mt][nt], a[mt], b0, b1);
            }
        }
        __syncthreads();
    }

    // epilogue: store feat (fp16) + accumulate el/er into smem
#pragma unroll
    for (int mt = 0; mt < 2; mt++) {
        int lr0 = wm * 32 + mt * 16 + gid;
        int lr1 = lr0 + 8;
        float el0 = 0.f, el1 = 0.f, er0 = 0.f, er1 = 0.f;
#pragma unroll
        for (int nt = 0; nt < 4; nt++) {
            int c = wn * 32 + nt * 8 + tig * 2;
            float alc0 = attn_l[c], alc1 = attn_l[c + 1];
            float arc0 = attn_r[c], arc1 = attn_r[c + 1];
            float* a4 = acc[mt][nt];
            el0 += a4[0] * alc0 + a4[1] * alc1;
            er0 += a4[0] * arc0 + a4[1] * arc1;
            el1 += a4[2] * alc0 + a4[3] * alc1;
            er1 += a4[2] * arc0 + a4[3] * arc1;
            *(__half2*)(g_featH + (size_t)(row0 + lr0) * 128 + c) =
                __floats2half2_rn(a4[0], a4[1]);
            *(__half2*)(g_featH + (size_t)(row0 + lr1) * 128 + c) =
                __floats2half2_rn(a4[2], a4[3]);
        }
        atomicAdd(&sEl[lr0][wn], el0);
        atomicAdd(&sEl[lr1][wn], el1);
        atomicAdd(&sEr[lr0][wn], er0);
        atomicAdd(&sEr[lr1][wn], er1);
    }
    __syncthreads();
    if (t < 64) {
        g_el[row0 + t] = make_float4(sEl[t][0], sEl[t][1], sEl[t][2], sEl[t][3]);
        g_er[row0 + t] = make_float4(sEr[t][0], sEr[t][1], sEr[t][2], sEr[t][3]);
    }
}

// ---------------- 2: fused edge-softmax + gather aggregation ----------------
// grid (Nc), 128 threads: block = one node, ALL 4 batches.
// thread: cp = tid&63 -> channels 2cp,2cp+1 ; bp = tid>>6 -> batches 2bp,2bp+1
// Softmax without max-subtraction: exp(e)/sum(exp(e)) identical; |e| small.
#define CHb 32
__global__ void __launch_bounds__(128, 8) k_agg(float* __restrict__ out) {
    const int n = blockIdx.x;
    const int tid = threadIdx.x;
    const int cp = tid & 63;
    const int bp = tid >> 6;
    const int h = cp >> 4;
    const int off0 = g_off[n];
    const int deg  = g_off[n + 1] - off0;
    const int b0 = 2 * bp, b1 = 2 * bp + 1;

    if (deg == 0) {
        *(float2*)(out + ((size_t)b0 * Nc + n) * 128 + cp * 2) = make_float2(0.f, 0.f);
        *(float2*)(out + ((size_t)b1 * Nc + n) * 128 + cp * 2) = make_float2(0.f, 0.f);
        return;
    }

    __shared__ int   ssrc[CHb];
    __shared__ float sw[CHb][4][4];   // [edge][batch][head]
    __shared__ float4 ser[4];

    if (tid < 4) ser[tid] = g_er[(size_t)tid * Nc + n];
    __syncthreads();

    float ax0 = 0.f, ay0 = 0.f, ax1 = 0.f, ay1 = 0.f;
    float ws0 = 0.f, ws1 = 0.f;

    for (int base = 0; base < deg; base += CHb) {
        int cnt = min(CHb, deg - base);
        {
            int e = tid & 31, b = tid >> 5;   // 32 edges x 4 batches
            if (e < cnt) {
                int s = g_csrc[off0 + base + e];
                if (b == 0) ssrc[e] = s;
                float4 el4 = g_el[(size_t)b * Nc + s];
                float4 er4 = ser[b];
                sw[e][b][0] = __expf(leaky(el4.x + er4.x, GAT_SLOPE));
                sw[e][b][1] = __expf(leaky(el4.y + er4.y, GAT_SLOPE));
                sw[e][b][2] = __expf(leaky(el4.z + er4.z, GAT_SLOPE));
                sw[e][b][3] = __expf(leaky(el4.w + er4.w, GAT_SLOPE));
            }
        }
        __syncthreads();
#pragma unroll 4
        for (int j = 0; j < cnt; j++) {
            int s = ssrc[j];
            float w0 = sw[j][b0][h];
            float w1 = sw[j][b1][h];
            ws0 += w0; ws1 += w1;
            __half2 f0 = *(const __half2*)(g_featH + ((size_t)b0 * Nc + s) * 128 + cp * 2);
            __half2 f1 = *(const __half2*)(g_featH + ((size_t)b1 * Nc + s) * 128 + cp * 2);
            float2 ff0 = __half22float2(f0);
            float2 ff1 = __half22float2(f1);
            ax0 += w0 * ff0.x; ay0 += w0 * ff0.y;
            ax1 += w1 * ff1.x; ay1 += w1 * ff1.y;
        }
        __syncthreads();
    }
    float inv0 = 1.f / fmaxf(ws0, 1e-9f);
    float inv1 = 1.f / fmaxf(ws1, 1e-9f);
    *(float2*)(out + ((size_t)b0 * Nc + n) * 128 + cp * 2) = make_float2(ax0 * inv0, ay0 * inv0);
    *(float2*)(out + ((size_t)b1 * Nc + n) * 128 + cp * 2) = make_float2(ax1 * inv1, ay1 * inv1);
}

// ---------------- 3: BN statistics -------------------------------------------
__global__ void k_bnstats(const float* __restrict__ out) {
    int c = threadIdx.x & 127;
    int r = blockIdx.x * 2 + (threadIdx.x >> 7);
    float s = 0.f, q = 0.f;
    for (; r < BNc; r += gridDim.x * 2) {
        float v = out[(size_t)r * 128 + c];
        s += v; q += v * v;
    }
    atomicAdd(&g_sum[c], s);
    atomicAdd(&g_sq[c], q);
}

__global__ void k_bnfinal(const float* __restrict__ gamma, const float* __restrict__ beta) {
    int c = threadIdx.x;
    float mean = g_sum[c] / (float)BNc;
    float var  = g_sq[c] / (float)BNc - mean * mean;
    float sc = gamma[c] * rsqrtf(var + BN_EPS);
    g_scale[c] = sc;
    g_shift[c] = beta[c] - mean * sc;
}

// ---------------- 4: BN apply + LeakyReLU (in place) -------------------------
__global__ void k_bnapply(float4* out) {
    int i = blockIdx.x * blockDim.x + threadIdx.x;
    int stride = gridDim.x * blockDim.x;
    const int n4 = BNc * HDc / 4;
    for (int p = i; p < n4; p += stride) {
        float4 v = out[p];
        int c = (p & 31) * 4;
        v.x = leaky(v.x * g_scale[c + 0] + g_shift[c + 0], ACT_SLOPE);
        v.y = leaky(v.y * g_scale[c + 1] + g_shift[c + 1], ACT_SLOPE);
        v.z = leaky(v.z * g_scale[c + 2] + g_shift[c + 2], ACT_SLOPE);
        v.w = leaky(v.w * g_scale[c + 3] + g_shift[c + 3], ACT_SLOPE);
        out[p] = v;
    }
}

// ---------------- launch -----------------------------------------------------
extern "C" void kernel_launch(void* const* d_in, const int* in_sizes, int n_in,
                              void* d_out, int out_size) {
    const float* xx     = (const float*)d_in[0];
    const float* W      = (const float*)d_in[1];
    const float* attn_l = (const float*)d_in[2];
    const float* attn_r = (const float*)d_in[3];
    const float* gamma  = (const float*)d_in[4];
    const float* beta   = (const float*)d_in[5];
    const int*   src    = (const int*)d_in[6];
    const int*   dst    = (const int*)d_in[7];
    float* out = (float*)d_out;
    const int E = in_sizes[6];

    static cudaStream_t s2 = nullptr;
    static cudaEvent_t evFork = nullptr, evJoin = nullptr;
    if (s2 == nullptr) {
        cudaStreamCreateWithFlags(&s2, cudaStreamNonBlocking);
        cudaEventCreateWithFlags(&evFork, cudaEventDisableTiming);
        cudaEventCreateWithFlags(&evJoin, cudaEventDisableTiming);
    }

    // fork: CSR build on s2, GEMM on main stream (independent work)
    cudaEventRecord(evFork, 0);
    cudaStreamWaitEvent(s2, evFork, 0);

    k_init<<<64, 256, 0, s2>>>();
    k_hist<<<(E + 511) / 512, 512, 0, s2>>>(dst, E);
    k_scan<<<1, 1024, 0, s2>>>();
    k_scatter<<<(E + 511) / 512, 512, 0, s2>>>(src, dst, E);
    cudaEventRecord(evJoin, s2);

    k_gemm<<<BNc / 64, 256>>>(xx, W, attn_l, attn_r);

    cudaStreamWaitEvent(0, evJoin, 0);

    k_agg<<<Nc, 128>>>(out);

    k_bnstats<<<1480, 256>>>(out);
    k_bnfinal<<<1, 128>>>(gamma, beta);
    k_bnapply<<<2048, 256>>>((float4*)out);
}

// round 9
// speedup vs baseline: 1.4350x; 1.1586x over previous
#include <cuda_runtime.h>
#include <cuda_fp16.h>
#include <math.h>

// Problem constants (fixed by the dataset)
#define Bc   4
#define Nc   50000
#define EcMax 800000
#define INc  128
#define Hc   4
#define Dc   32
#define HDc  128
#define BNc  (Bc * Nc)          // 200000 rows
#define GAT_SLOPE 0.2f
#define ACT_SLOPE 0.01f
#define BN_EPS    1e-5f
#define NSLICE 8

// ---------------- scratch (device globals; no allocation allowed) ----------
__device__ __half   g_featH[(size_t)BNc * HDc]; // 51.2 MB (fp16 features)
__device__ float4   g_el[BNc];                  // per-node, per-head (4 heads)
__device__ float4   g_er[BNc];
__device__ int      g_cnt[Nc];                  // in-degree histogram
__device__ int      g_off[Nc + 1];              // CSR offsets
__device__ int      g_wr[Nc];                   // scatter write cursors
__device__ int      g_csrc[EcMax];              // CSR: src node per slot
__device__ float    g_psum[NSLICE][HDc];        // sliced BN sum accumulators
__device__ float    g_psq[NSLICE][HDc];         // sliced BN sq accumulators
__device__ float    g_scale[HDc];
__device__ float    g_shift[HDc];

__device__ __forceinline__ float leaky(float v, float s) {
    return v >= 0.0f ? v : s * v;
}

__device__ __forceinline__ unsigned f2tf32(float f) {
    unsigned u;
    asm("cvt.rna.tf32.f32 %0, %1;" : "=r"(u) : "f"(f));
    return u;
}

__device__ __forceinline__ void mma_tf32(float* c, const unsigned* a,
                                         unsigned b0, unsigned b1) {
    asm volatile(
        "mma.sync.aligned.m16n8k8.row.col.f32.tf32.tf32.f32 "
        "{%0,%1,%2,%3}, {%4,%5,%6,%7}, {%8,%9}, {%0,%1,%2,%3};"
        : "+f"(c[0]), "+f"(c[1]), "+f"(c[2]), "+f"(c[3])
        : "r"(a[0]), "r"(a[1]), "r"(a[2]), "r"(a[3]), "r"(b0), "r"(b1));
}

// ---------------- 0: zero-init histogram + BN accumulators ------------------
__global__ void k_init() {
    int i = blockIdx.x * blockDim.x + threadIdx.x;
    int stride = gridDim.x * blockDim.x;
    for (int p = i; p < Nc; p += stride) g_cnt[p] = 0;
    if (i < NSLICE * HDc) {
        ((float*)g_psum)[i] = 0.f;
        ((float*)g_psq)[i] = 0.f;
    }
}

// ---------------- CSR build --------------------------------------------------
__global__ void k_hist(const int* __restrict__ dst, int E) {
    int e = blockIdx.x * blockDim.x + threadIdx.x;
    if (e < E) atomicAdd(&g_cnt[dst[e]], 1);
}

__global__ void k_scan() {
    __shared__ int ssum[1024];
    const int t = threadIdx.x;
    const int per = (Nc + 1023) / 1024;   // 49
    const int base = t * per;
    int s = 0;
    for (int i = 0; i < per; i++) {
        int idx = base + i;
        if (idx < Nc) s += g_cnt[idx];
    }
    ssum[t] = s;
    __syncthreads();
    for (int o = 1; o < 1024; o <<= 1) {
        int v = (t >= o) ? ssum[t - o] : 0;
        __syncthreads();
        ssum[t] += v;
        __syncthreads();
    }
    int run = ssum[t] - s;
    for (int i = 0; i < per; i++) {
        int idx = base + i;
        if (idx < Nc) {
            g_off[idx] = run;
            g_wr[idx]  = run;
            run += g_cnt[idx];
        }
    }
    if (t == 1023) g_off[Nc] = ssum[1023];
}

__global__ void k_scatter(const int* __restrict__ src, const int* __restrict__ dst, int E) {
    int e = blockIdx.x * blockDim.x + threadIdx.x;
    if (e < E) {
        int pos = atomicAdd(&g_wr[dst[e]], 1);
        g_csrc[pos] = src[e];
    }
}

// ---------------- 1: feat = x @ W via tf32 mma, fused el/er epilogue --------
// Block 256 threads (8 warps, 2m x 4n), block tile 64x128, warp tile 32x32.
// 200000 rows = 3125 * 64 exactly: no row guards needed.
__global__ void __launch_bounds__(256, 3)
k_gemm(const float* __restrict__ x, const float* __restrict__ W,
       const float* __restrict__ attn_l, const float* __restrict__ attn_r) {
    __shared__ float xs[64][36];     // [row][k], pad 36
    __shared__ float Ws[32][136];    // [k][col], pad 136
    __shared__ float sEl[64][4];
    __shared__ float sEr[64][4];

    const int t = threadIdx.x;
    const int lane = t & 31, warp = t >> 5;
    const int wm = warp >> 2, wn = warp & 3;   // warp grid 2m x 4n
    const int gid = lane >> 2, tig = lane & 3;
    const int row0 = blockIdx.x * 64;

    ((float*)sEl)[t] = 0.f;
    ((float*)sEr)[t] = 0.f;

    float acc[2][4][4];
#pragma unroll
    for (int i = 0; i < 2; i++)
#pragma unroll
        for (int j = 0; j < 4; j++)
#pragma unroll
            for (int r = 0; r < 4; r++) acc[i][j][r] = 0.f;

    for (int kc = 0; kc < 128; kc += 32) {
#pragma unroll
        for (int i = 0; i < 4; i++) {
            int idx = i * 256 + t;
            int k = idx >> 5, c4 = idx & 31;
            float4 v = *(const float4*)(W + (size_t)(kc + k) * 128 + c4 * 4);
            float* dstp = &Ws[k][c4 * 4];
            dstp[0] = __uint_as_float(f2tf32(v.x));
            dstp[1] = __uint_as_float(f2tf32(v.y));
            dstp[2] = __uint_as_float(f2tf32(v.z));
            dstp[3] = __uint_as_float(f2tf32(v.w));
        }
#pragma unroll
        for (int i = 0; i < 2; i++) {
            int idx = i * 256 + t;
            int r = idx >> 3, c4 = idx & 7;
            float4 v = *(const float4*)(x + (size_t)(row0 + r) * 128 + kc + c4 * 4);
            float* dstp = &xs[r][c4 * 4];
            dstp[0] = __uint_as_float(f2tf32(v.x));
            dstp[1] = __uint_as_float(f2tf32(v.y));
            dstp[2] = __uint_as_float(f2tf32(v.z));
            dstp[3] = __uint_as_float(f2tf32(v.w));
        }
        __syncthreads();

#pragma unroll
        for (int ks = 0; ks < 4; ks++) {
            const int k0 = ks * 8;
            unsigned a[2][4];
#pragma unroll
            for (int mt = 0; mt < 2; mt++) {
                int rb = wm * 32 + mt * 16;
                a[mt][0] = __float_as_uint(xs[rb + gid][k0 + tig]);
                a[mt][1] = __float_as_uint(xs[rb + gid + 8][k0 + tig]);
                a[mt][2] = __float_as_uint(xs[rb + gid][k0 + tig + 4]);
                a[mt][3] = __float_as_uint(xs[rb + gid + 8][k0 + tig + 4]);
            }
#pragma unroll
            for (int nt = 0; nt < 4; nt++) {
                int cb = wn * 32 + nt * 8;
                unsigned b0 = __float_as_uint(Ws[k0 + tig][cb + gid]);
                unsigned b1 = __float_as_uint(Ws[k0 + tig + 4][cb + gid]);
#pragma unroll
                for (int mt = 0; mt < 2; mt++)
                    mma_tf32(acc[mt][nt], a[mt], b0, b1);
            }
        }
        __syncthreads();
    }

    // epilogue: store feat (fp16) + accumulate el/er into smem
#pragma unroll
    for (int mt = 0; mt < 2; mt++) {
        int lr0 = wm * 32 + mt * 16 + gid;
        int lr1 = lr0 + 8;
        float el0 = 0.f, el1 = 0.f, er0 = 0.f, er1 = 0.f;
#pragma unroll
        for (int nt = 0; nt < 4; nt++) {
            int c = wn * 32 + nt * 8 + tig * 2;
            float alc0 = attn_l[c], alc1 = attn_l[c + 1];
            float arc0 = attn_r[c], arc1 = attn_r[c + 1];
            float* a4 = acc[mt][nt];
            el0 += a4[0] * alc0 + a4[1] * alc1;
            er0 += a4[0] * arc0 + a4[1] * arc1;
            el1 += a4[2] * alc0 + a4[3] * alc1;
            er1 += a4[2] * arc0 + a4[3] * arc1;
            *(__half2*)(g_featH + (size_t)(row0 + lr0) * 128 + c) =
                __floats2half2_rn(a4[0], a4[1]);
            *(__half2*)(g_featH + (size_t)(row0 + lr1) * 128 + c) =
                __floats2half2_rn(a4[2], a4[3]);
        }
        atomicAdd(&sEl[lr0][wn], el0);
        atomicAdd(&sEl[lr1][wn], el1);
        atomicAdd(&sEr[lr0][wn], er0);
        atomicAdd(&sEr[lr1][wn], er1);
    }
    __syncthreads();
    if (t < 64) {
        g_el[row0 + t] = make_float4(sEl[t][0], sEl[t][1], sEl[t][2], sEl[t][3]);
        g_er[row0 + t] = make_float4(sEr[t][0], sEr[t][1], sEr[t][2], sEr[t][3]);
    }
}

// ---------------- 2: fused edge-softmax + gather agg + BN partial stats -----
// grid (Nc), 128 threads: block = one node, ALL 4 batches.
// thread: cp = tid&63 -> channels 2cp,2cp+1 ; bp = tid>>6 -> batches 2bp,2bp+1
// Softmax without max-subtraction: exp(e)/sum(exp(e)) identical; |e| small.
// BN stats: per-block smem pre-reduce (unique slots), then 2 atomicAdds per
// thread into 8-way-sliced global accumulators.
#define CHb 32
__global__ void __launch_bounds__(128, 8) k_agg(float* __restrict__ out) {
    const int n = blockIdx.x;
    const int tid = threadIdx.x;
    const int cp = tid & 63;
    const int bp = tid >> 6;
    const int h = cp >> 4;
    const int off0 = g_off[n];
    const int deg  = g_off[n + 1] - off0;
    const int b0 = 2 * bp, b1 = 2 * bp + 1;

    if (deg == 0) {
        // zero outputs contribute nothing to BN sums (g_psum pre-zeroed)
        *(float2*)(out + ((size_t)b0 * Nc + n) * 128 + cp * 2) = make_float2(0.f, 0.f);
        *(float2*)(out + ((size_t)b1 * Nc + n) * 128 + cp * 2) = make_float2(0.f, 0.f);
        return;
    }

    __shared__ int   ssrc[CHb];
    __shared__ float sw[CHb][4][4];   // [edge][batch][head]
    __shared__ float4 ser[4];
    __shared__ float sS[2][HDc];      // [bp][channel] partial sums
    __shared__ float sQ[2][HDc];      // [bp][channel] partial sq

    if (tid < 4) ser[tid] = g_er[(size_t)tid * Nc + n];
    __syncthreads();

    float ax0 = 0.f, ay0 = 0.f, ax1 = 0.f, ay1 = 0.f;
    float ws0 = 0.f, ws1 = 0.f;

    for (int base = 0; base < deg; base += CHb) {
        int cnt = min(CHb, deg - base);
        {
            int e = tid & 31, b = tid >> 5;   // 32 edges x 4 batches
            if (e < cnt) {
                int s = g_csrc[off0 + base + e];
                if (b == 0) ssrc[e] = s;
                float4 el4 = g_el[(size_t)b * Nc + s];
                float4 er4 = ser[b];
                sw[e][b][0] = __expf(leaky(el4.x + er4.x, GAT_SLOPE));
                sw[e][b][1] = __expf(leaky(el4.y + er4.y, GAT_SLOPE));
                sw[e][b][2] = __expf(leaky(el4.z + er4.z, GAT_SLOPE));
                sw[e][b][3] = __expf(leaky(el4.w + er4.w, GAT_SLOPE));
            }
        }
        __syncthreads();
#pragma unroll 4
        for (int j = 0; j < cnt; j++) {
            int s = ssrc[j];
            float w0 = sw[j][b0][h];
            float w1 = sw[j][b1][h];
            ws0 += w0; ws1 += w1;
            __half2 f0 = *(const __half2*)(g_featH + ((size_t)b0 * Nc + s) * 128 + cp * 2);
            __half2 f1 = *(const __half2*)(g_featH + ((size_t)b1 * Nc + s) * 128 + cp * 2);
            float2 ff0 = __half22float2(f0);
            float2 ff1 = __half22float2(f1);
            ax0 += w0 * ff0.x; ay0 += w0 * ff0.y;
            ax1 += w1 * ff1.x; ay1 += w1 * ff1.y;
        }
        __syncthreads();
    }
    float inv0 = 1.f / fmaxf(ws0, 1e-9f);
    float inv1 = 1.f / fmaxf(ws1, 1e-9f);
    float o0x = ax0 * inv0, o0y = ay0 * inv0;
    float o1x = ax1 * inv1, o1y = ay1 * inv1;
    *(float2*)(out + ((size_t)b0 * Nc + n) * 128 + cp * 2) = make_float2(o0x, o0y);
    *(float2*)(out + ((size_t)b1 * Nc + n) * 128 + cp * 2) = make_float2(o1x, o1y);

    // BN partial stats: this thread covers channels (2cp, 2cp+1) for 2 batches
    sS[bp][2 * cp + 0] = o0x + o1x;
    sS[bp][2 * cp + 1] = o0y + o1y;
    sQ[bp][2 * cp + 0] = o0x * o0x + o1x * o1x;
    sQ[bp][2 * cp + 1] = o0y * o0y + o1y * o1y;
    __syncthreads();
    {
        int ch = tid;  // 128 threads, 128 channels
        int sl = n & (NSLICE - 1);
        atomicAdd(&g_psum[sl][ch], sS[0][ch] + sS[1][ch]);
        atomicAdd(&g_psq[sl][ch],  sQ[0][ch] + sQ[1][ch]);
    }
}

// ---------------- 3: finalize BN coefficients --------------------------------
__global__ void k_bnfinal(const float* __restrict__ gamma, const float* __restrict__ beta) {
    int c = threadIdx.x;
    float s = 0.f, q = 0.f;
#pragma unroll
    for (int i = 0; i < NSLICE; i++) { s += g_psum[i][c]; q += g_psq[i][c]; }
    float mean = s / (float)BNc;
    float var  = q / (float)BNc - mean * mean;
    float sc = gamma[c] * rsqrtf(var + BN_EPS);
    g_scale[c] = sc;
    g_shift[c] = beta[c] - mean * sc;
}

// ---------------- 4: BN apply + LeakyReLU (in place) -------------------------
__global__ void k_bnapply(float4* out) {
    int i = blockIdx.x * blockDim.x + threadIdx.x;
    int stride = gridDim.x * blockDim.x;
    const int n4 = BNc * HDc / 4;
    for (int p = i; p < n4; p += stride) {
        float4 v = out[p];
        int c = (p & 31) * 4;
        v.x = leaky(v.x * g_scale[c + 0] + g_shift[c + 0], ACT_SLOPE);
        v.y = leaky(v.y * g_scale[c + 1] + g_shift[c + 1], ACT_SLOPE);
        v.z = leaky(v.z * g_scale[c + 2] + g_shift[c + 2], ACT_SLOPE);
        v.w = leaky(v.w * g_scale[c + 3] + g_shift[c + 3], ACT_SLOPE);
        out[p] = v;
    }
}

// ---------------- launch -----------------------------------------------------
extern "C" void kernel_launch(void* const* d_in, const int* in_sizes, int n_in,
                              void* d_out, int out_size) {
    const float* xx     = (const float*)d_in[0];
    const float* W      = (const float*)d_in[1];
    const float* attn_l = (const float*)d_in[2];
    const float* attn_r = (const float*)d_in[3];
    const float* gamma  = (const float*)d_in[4];
    const float* beta   = (const float*)d_in[5];
    const int*   src    = (const int*)d_in[6];
    const int*   dst    = (const int*)d_in[7];
    float* out = (float*)d_out;
    const int E = in_sizes[6];

    static cudaStream_t s2 = nullptr;
    static cudaEvent_t evFork = nullptr, evJoin = nullptr;
    if (s2 == nullptr) {
        cudaStreamCreateWithFlags(&s2, cudaStreamNonBlocking);
        cudaEventCreateWithFlags(&evFork, cudaEventDisableTiming);
        cudaEventCreateWithFlags(&evJoin, cudaEventDisableTiming);
    }

    // fork: CSR build on s2, GEMM on main stream (independent work)
    cudaEventRecord(evFork, 0);
    cudaStreamWaitEvent(s2, evFork, 0);

    k_init<<<64, 256, 0, s2>>>();
    k_hist<<<(E + 511) / 512, 512, 0, s2>>>(dst, E);
    k_scan<<<1, 1024, 0, s2>>>();
    k_scatter<<<(E + 511) / 512, 512, 0, s2>>>(src, dst, E);
    cudaEventRecord(evJoin, s2);

    k_gemm<<<BNc / 64, 256>>>(xx, W, attn_l, attn_r);

    cudaStreamWaitEvent(0, evJoin, 0);

    k_agg<<<Nc, 128>>>(out);

    k_bnfinal<<<1, 128>>>(gamma, beta);
    k_bnapply<<<2048, 256>>>((float4*)out);
}

// round 10
// speedup vs baseline: 1.5851x; 1.1046x over previous
#include <cuda_runtime.h>
#include <cuda_fp16.h>
#include <math.h>

// Problem constants (fixed by the dataset)
#define Bc   4
#define Nc   50000
#define EcMax 800000
#define INc  128
#define Hc   4
#define Dc   32
#define HDc  128
#define BNc  (Bc * Nc)          // 200000 rows
#define GAT_SLOPE 0.2f
#define ACT_SLOPE 0.01f
#define BN_EPS    1e-5f
#define NSLICE 8

// ---------------- scratch (device globals; no allocation allowed) ----------
__device__ __half   g_featH[(size_t)BNc * HDc]; // 51.2 MB (fp16 features)
__device__ float4   g_el[BNc];                  // per-node, per-head (4 heads)
__device__ float4   g_er[BNc];
__device__ int      g_cnt[Nc];                  // in-degree histogram
__device__ int      g_off[Nc + 1];              // CSR offsets
__device__ int      g_wr[Nc];                   // scatter write cursors
__device__ int      g_csrc[EcMax];              // CSR: src node per slot
__device__ float    g_psum[NSLICE][HDc];        // sliced BN sum accumulators
__device__ float    g_psq[NSLICE][HDc];         // sliced BN sq accumulators
__device__ float    g_scale[HDc];
__device__ float    g_shift[HDc];

__device__ __forceinline__ float leaky(float v, float s) {
    return v >= 0.0f ? v : s * v;
}

__device__ __forceinline__ unsigned f2tf32(float f) {
    unsigned u;
    asm("cvt.rna.tf32.f32 %0, %1;" : "=r"(u) : "f"(f));
    return u;
}

__device__ __forceinline__ void mma_tf32(float* c, const unsigned* a,
                                         unsigned b0, unsigned b1) {
    asm volatile(
        "mma.sync.aligned.m16n8k8.row.col.f32.tf32.tf32.f32 "
        "{%0,%1,%2,%3}, {%4,%5,%6,%7}, {%8,%9}, {%0,%1,%2,%3};"
        : "+f"(c[0]), "+f"(c[1]), "+f"(c[2]), "+f"(c[3])
        : "r"(a[0]), "r"(a[1]), "r"(a[2]), "r"(a[3]), "r"(b0), "r"(b1));
}

// ---------------- 0: zero-init histogram + BN accumulators ------------------
__global__ void k_init() {
    int i = blockIdx.x * blockDim.x + threadIdx.x;
    int stride = gridDim.x * blockDim.x;
    for (int p = i; p < Nc; p += stride) g_cnt[p] = 0;
    if (i < NSLICE * HDc) {
        ((float*)g_psum)[i] = 0.f;
        ((float*)g_psq)[i] = 0.f;
    }
}

// ---------------- CSR build --------------------------------------------------
__global__ void k_hist(const int* __restrict__ dst, int E) {
    int e = blockIdx.x * blockDim.x + threadIdx.x;
    if (e < E) atomicAdd(&g_cnt[dst[e]], 1);
}

__global__ void k_scan() {
    __shared__ int ssum[1024];
    const int t = threadIdx.x;
    const int per = (Nc + 1023) / 1024;   // 49
    const int base = t * per;
    int s = 0;
    for (int i = 0; i < per; i++) {
        int idx = base + i;
        if (idx < Nc) s += g_cnt[idx];
    }
    ssum[t] = s;
    __syncthreads();
    for (int o = 1; o < 1024; o <<= 1) {
        int v = (t >= o) ? ssum[t - o] : 0;
        __syncthreads();
        ssum[t] += v;
        __syncthreads();
    }
    int run = ssum[t] - s;
    for (int i = 0; i < per; i++) {
        int idx = base + i;
        if (idx < Nc) {
            g_off[idx] = run;
            g_wr[idx]  = run;
            run += g_cnt[idx];
        }
    }
    if (t == 1023) g_off[Nc] = ssum[1023];
}

__global__ void k_scatter(const int* __restrict__ src, const int* __restrict__ dst, int E) {
    int e = blockIdx.x * blockDim.x + threadIdx.x;
    if (e < E) {
        int pos = atomicAdd(&g_wr[dst[e]], 1);
        g_csrc[pos] = src[e];
    }
}

// ---------------- 1: feat = x @ W via tf32 mma, fused el/er epilogue --------
// Block 256 threads (8 warps, 2m x 4n), block tile 64x128, warp tile 32x32.
// 200000 rows = 3125 * 64 exactly: no row guards needed.
__global__ void __launch_bounds__(256, 3)
k_gemm(const float* __restrict__ x, const float* __restrict__ W,
       const float* __restrict__ attn_l, const float* __restrict__ attn_r) {
    __shared__ float xs[64][36];     // [row][k], pad 36
    __shared__ float Ws[32][136];    // [k][col], pad 136
    __shared__ float sEl[64][4];
    __shared__ float sEr[64][4];

    const int t = threadIdx.x;
    const int lane = t & 31, warp = t >> 5;
    const int wm = warp >> 2, wn = warp & 3;   // warp grid 2m x 4n
    const int gid = lane >> 2, tig = lane & 3;
    const int row0 = blockIdx.x * 64;

    ((float*)sEl)[t] = 0.f;
    ((float*)sEr)[t] = 0.f;

    float acc[2][4][4];
#pragma unroll
    for (int i = 0; i < 2; i++)
#pragma unroll
        for (int j = 0; j < 4; j++)
#pragma unroll
            for (int r = 0; r < 4; r++) acc[i][j][r] = 0.f;

    for (int kc = 0; kc < 128; kc += 32) {
#pragma unroll
        for (int i = 0; i < 4; i++) {
            int idx = i * 256 + t;
            int k = idx >> 5, c4 = idx & 31;
            float4 v = *(const float4*)(W + (size_t)(kc + k) * 128 + c4 * 4);
            float* dstp = &Ws[k][c4 * 4];
            dstp[0] = __uint_as_float(f2tf32(v.x));
            dstp[1] = __uint_as_float(f2tf32(v.y));
            dstp[2] = __uint_as_float(f2tf32(v.z));
            dstp[3] = __uint_as_float(f2tf32(v.w));
        }
#pragma unroll
        for (int i = 0; i < 2; i++) {
            int idx = i * 256 + t;
            int r = idx >> 3, c4 = idx & 7;
            float4 v = *(const float4*)(x + (size_t)(row0 + r) * 128 + kc + c4 * 4);
            float* dstp = &xs[r][c4 * 4];
            dstp[0] = __uint_as_float(f2tf32(v.x));
            dstp[1] = __uint_as_float(f2tf32(v.y));
            dstp[2] = __uint_as_float(f2tf32(v.z));
            dstp[3] = __uint_as_float(f2tf32(v.w));
        }
        __syncthreads();

#pragma unroll
        for (int ks = 0; ks < 4; ks++) {
            const int k0 = ks * 8;
            unsigned a[2][4];
#pragma unroll
            for (int mt = 0; mt < 2; mt++) {
                int rb = wm * 32 + mt * 16;
                a[mt][0] = __float_as_uint(xs[rb + gid][k0 + tig]);
                a[mt][1] = __float_as_uint(xs[rb + gid + 8][k0 + tig]);
                a[mt][2] = __float_as_uint(xs[rb + gid][k0 + tig + 4]);
                a[mt][3] = __float_as_uint(xs[rb + gid + 8][k0 + tig + 4]);
            }
#pragma unroll
            for (int nt = 0; nt < 4; nt++) {
                int cb = wn * 32 + nt * 8;
                unsigned b0 = __float_as_uint(Ws[k0 + tig][cb + gid]);
                unsigned b1 = __float_as_uint(Ws[k0 + tig + 4][cb + gid]);
#pragma unroll
                for (int mt = 0; mt < 2; mt++)
                    mma_tf32(acc[mt][nt], a[mt], b0, b1);
            }
        }
        __syncthreads();
    }

    // epilogue: store feat (fp16) + accumulate el/er into smem
#pragma unroll
    for (int mt = 0; mt < 2; mt++) {
        int lr0 = wm * 32 + mt * 16 + gid;
        int lr1 = lr0 + 8;
        float el0 = 0.f, el1 = 0.f, er0 = 0.f, er1 = 0.f;
#pragma unroll
        for (int nt = 0; nt < 4; nt++) {
            int c = wn * 32 + nt * 8 + tig * 2;
            float alc0 = attn_l[c], alc1 = attn_l[c + 1];
            float arc0 = attn_r[c], arc1 = attn_r[c + 1];
            float* a4 = acc[mt][nt];
            el0 += a4[0] * alc0 + a4[1] * alc1;
            er0 += a4[0] * arc0 + a4[1] * arc1;
            el1 += a4[2] * alc0 + a4[3] * alc1;
            er1 += a4[2] * arc0 + a4[3] * arc1;
            *(__half2*)(g_featH + (size_t)(row0 + lr0) * 128 + c) =
                __floats2half2_rn(a4[0], a4[1]);
            *(__half2*)(g_featH + (size_t)(row0 + lr1) * 128 + c) =
                __floats2half2_rn(a4[2], a4[3]);
        }
        atomicAdd(&sEl[lr0][wn], el0);
        atomicAdd(&sEl[lr1][wn], el1);
        atomicAdd(&sEr[lr0][wn], er0);
        atomicAdd(&sEr[lr1][wn], er1);
    }
    __syncthreads();
    if (t < 64) {
        g_el[row0 + t] = make_float4(sEl[t][0], sEl[t][1], sEl[t][2], sEl[t][3]);
        g_er[row0 + t] = make_float4(sEr[t][0], sEr[t][1], sEr[t][2], sEr[t][3]);
    }
}

// ---------------- 2: fused edge-softmax + gather agg + BN partial stats -----
// grid (Nc), 128 threads: block = one node, ALL 4 batches.
// __launch_bounds__(128,16): 2048 threads/SM (was 1024) — doubles the number
// of concurrent gather chains covering L2 latency.
#define CHb 32
__global__ void __launch_bounds__(128, 16) k_agg(float* __restrict__ out) {
    const int n = blockIdx.x;
    const int tid = threadIdx.x;
    const int cp = tid & 63;
    const int bp = tid >> 6;
    const int h = cp >> 4;
    const int off0 = g_off[n];
    const int deg  = g_off[n + 1] - off0;
    const int b0 = 2 * bp, b1 = 2 * bp + 1;

    if (deg == 0) {
        *(float2*)(out + ((size_t)b0 * Nc + n) * 128 + cp * 2) = make_float2(0.f, 0.f);
        *(float2*)(out + ((size_t)b1 * Nc + n) * 128 + cp * 2) = make_float2(0.f, 0.f);
        return;
    }

    __shared__ int   ssrc[CHb];
    __shared__ float sw[CHb][4][4];   // [edge][batch][head]
    __shared__ float4 ser[4];
    __shared__ float sS[2][HDc];      // [bp][channel] partial sums
    __shared__ float sQ[2][HDc];      // [bp][channel] partial sq

    if (tid < 4) ser[tid] = g_er[(size_t)tid * Nc + n];
    __syncthreads();

    float ax0 = 0.f, ay0 = 0.f, ax1 = 0.f, ay1 = 0.f;
    float ws0 = 0.f, ws1 = 0.f;

    for (int base = 0; base < deg; base += CHb) {
        int cnt = min(CHb, deg - base);
        {
            int e = tid & 31, b = tid >> 5;   // 32 edges x 4 batches
            if (e < cnt) {
                int s = g_csrc[off0 + base + e];
                if (b == 0) ssrc[e] = s;
                float4 el4 = g_el[(size_t)b * Nc + s];
                float4 er4 = ser[b];
                sw[e][b][0] = __expf(leaky(el4.x + er4.x, GAT_SLOPE));
                sw[e][b][1] = __expf(leaky(el4.y + er4.y, GAT_SLOPE));
                sw[e][b][2] = __expf(leaky(el4.z + er4.z, GAT_SLOPE));
                sw[e][b][3] = __expf(leaky(el4.w + er4.w, GAT_SLOPE));
            }
        }
        __syncthreads();
#pragma unroll 4
        for (int j = 0; j < cnt; j++) {
            int s = ssrc[j];
            float w0 = sw[j][b0][h];
            float w1 = sw[j][b1][h];
            ws0 += w0; ws1 += w1;
            __half2 f0 = *(const __half2*)(g_featH + ((size_t)b0 * Nc + s) * 128 + cp * 2);
            __half2 f1 = *(const __half2*)(g_featH + ((size_t)b1 * Nc + s) * 128 + cp * 2);
            float2 ff0 = __half22float2(f0);
            float2 ff1 = __half22float2(f1);
            ax0 += w0 * ff0.x; ay0 += w0 * ff0.y;
            ax1 += w1 * ff1.x; ay1 += w1 * ff1.y;
        }
        __syncthreads();
    }
    float inv0 = 1.f / fmaxf(ws0, 1e-9f);
    float inv1 = 1.f / fmaxf(ws1, 1e-9f);
    float o0x = ax0 * inv0, o0y = ay0 * inv0;
    float o1x = ax1 * inv1, o1y = ay1 * inv1;
    *(float2*)(out + ((size_t)b0 * Nc + n) * 128 + cp * 2) = make_float2(o0x, o0y);
    *(float2*)(out + ((size_t)b1 * Nc + n) * 128 + cp * 2) = make_float2(o1x, o1y);

    // BN partial stats: smem pre-reduce, then 2 sliced global atomics/thread
    sS[bp][2 * cp + 0] = o0x + o1x;
    sS[bp][2 * cp + 1] = o0y + o1y;
    sQ[bp][2 * cp + 0] = o0x * o0x + o1x * o1x;
    sQ[bp][2 * cp + 1] = o0y * o0y + o1y * o1y;
    __syncthreads();
    {
        int ch = tid;  // 128 threads, 128 channels
        int sl = n & (NSLICE - 1);
        atomicAdd(&g_psum[sl][ch], sS[0][ch] + sS[1][ch]);
        atomicAdd(&g_psq[sl][ch],  sQ[0][ch] + sQ[1][ch]);
    }
}

// ---------------- 3: finalize BN coefficients --------------------------------
__global__ void k_bnfinal(const float* __restrict__ gamma, const float* __restrict__ beta) {
    int c = threadIdx.x;
    float s = 0.f, q = 0.f;
#pragma unroll
    for (int i = 0; i < NSLICE; i++) { s += g_psum[i][c]; q += g_psq[i][c]; }
    float mean = s / (float)BNc;
    float var  = q / (float)BNc - mean * mean;
    float sc = gamma[c] * rsqrtf(var + BN_EPS);
    g_scale[c] = sc;
    g_shift[c] = beta[c] - mean * sc;
}

// ---------------- 4: BN apply + LeakyReLU (channel-stationary) ---------------
// Thread owns one float4 channel slot: scale/shift live in registers across
// the whole row loop. 256 threads = 8 rows per block-iteration.
__global__ void __launch_bounds__(256) k_bnapply(float4* out) {
    const int c4 = threadIdx.x & 31;
    const float4 sc = *(const float4*)(g_scale + c4 * 4);
    const float4 sh = *(const float4*)(g_shift + c4 * 4);
    int r = blockIdx.x * 8 + (threadIdx.x >> 5);
    const int rstride = gridDim.x * 8;
    for (; r < BNc; r += rstride) {
        float4 v = out[(size_t)r * 32 + c4];
        v.x = leaky(v.x * sc.x + sh.x, ACT_SLOPE);
        v.y = leaky(v.y * sc.y + sh.y, ACT_SLOPE);
        v.z = leaky(v.z * sc.z + sh.z, ACT_SLOPE);
        v.w = leaky(v.w * sc.w + sh.w, ACT_SLOPE);
        out[(size_t)r * 32 + c4] = v;
    }
}

// ---------------- launch -----------------------------------------------------
extern "C" void kernel_launch(void* const* d_in, const int* in_sizes, int n_in,
                              void* d_out, int out_size) {
    const float* xx     = (const float*)d_in[0];
    const float* W      = (const float*)d_in[1];
    const float* attn_l = (const float*)d_in[2];
    const float* attn_r = (const float*)d_in[3];
    const float* gamma  = (const float*)d_in[4];
    const float* beta   = (const float*)d_in[5];
    const int*   src    = (const int*)d_in[6];
    const int*   dst    = (const int*)d_in[7];
    float* out = (float*)d_out;
    const int E = in_sizes[6];

    static cudaStream_t s2 = nullptr;
    static cudaEvent_t evFork = nullptr, evJoin = nullptr;
    if (s2 == nullptr) {
        cudaStreamCreateWithFlags(&s2, cudaStreamNonBlocking);
        cudaEventCreateWithFlags(&evFork, cudaEventDisableTiming);
        cudaEventCreateWithFlags(&evJoin, cudaEventDisableTiming);
    }

    // fork: CSR build on s2, GEMM on main stream (independent work)
    cudaEventRecord(evFork, 0);
    cudaStreamWaitEvent(s2, evFork, 0);

    k_init<<<64, 256, 0, s2>>>();
    k_hist<<<(E + 511) / 512, 512, 0, s2>>>(dst, E);
    k_scan<<<1, 1024, 0, s2>>>();
    k_scatter<<<(E + 511) / 512, 512, 0, s2>>>(src, dst, E);
    cudaEventRecord(evJoin, s2);

    k_gemm<<<BNc / 64, 256>>>(xx, W, attn_l, attn_r);

    cudaStreamWaitEvent(0, evJoin, 0);

    k_agg<<<Nc, 128>>>(out);

    k_bnfinal<<<1, 128>>>(gamma, beta);
    k_bnapply<<<2048, 256>>>((float4*)out);
}